// round 13
// baseline (speedup 1.0000x reference)
#include <cuda_runtime.h>
#include <cuda_fp16.h>
#include <cstdint>

// Problem constants
static constexpr int Bb = 4;
static constexpr int Cc = 256;
static constexpr int Dd = 128;
static constexpr int Nn = 4096;
static constexpr int Mm = Nn - 1;    // 4095

// Scratch (device globals; no runtime allocation allowed)
__device__ float g_theta[Bb * Nn * Dd];
__device__ float g_phi  [Bb * Nn * Dd];
__device__ float g_g    [Bb * Nn * Dd];
// x split to fp16 hi/lo [16384][256]
__device__ __half g_x_hi[Bb * Nn * Cc];
__device__ __half g_x_lo[Bb * Nn * Cc];
// Wt/Wp/Wg transposed [z][n=128][k=256], split hi/lo
__device__ __half g_wT_hi[3 * Dd * Cc];
__device__ __half g_wT_lo[3 * Dd * Cc];
// Wf transposed [n=256][k=128], split hi/lo
__device__ __half g_wfT_hi[Cc * Dd];
__device__ __half g_wfT_lo[Cc * Dd];
// y (attention output) split fp16 hi/lo [16384][128]
__device__ __half g_y_hi[Bb * Nn * Dd];
__device__ __half g_y_lo[Bb * Nn * Dd];
// pooled phi, split to fp16 hi/lo, padded to 4096 rows (row 4095 = 0)
__device__ __half g_ph_hi[Bb * Nn * Dd];
__device__ __half g_ph_lo[Bb * Nn * Dd];
// pooled g, TRANSPOSED [b][d=128][key=4096], split hi/lo, key 4095 = 0
__device__ __half g_gT_hi[Bb * Dd * Nn];
__device__ __half g_gT_lo[Bb * Dd * Nn];

// ===========================================================================
// Helpers
// ===========================================================================
__device__ __forceinline__ uint32_t smem_to_u32(const void* p) {
    uint32_t a;
    asm("{ .reg .u64 t; cvta.to.shared.u64 t, %1; cvt.u32.u64 %0, t; }"
        : "=r"(a) : "l"(p));
    return a;
}

#define CP_ASYNC16(dst_u32, src_ptr) \
    asm volatile("cp.async.cg.shared.global [%0], [%1], 16;" \
        :: "r"(dst_u32), "l"(src_ptr) : "memory")
#define CP_COMMIT() asm volatile("cp.async.commit_group;" ::: "memory")
#define CP_WAIT1()  asm volatile("cp.async.wait_group 1;" ::: "memory")
#define CP_WAIT0()  asm volatile("cp.async.wait_group 0;" ::: "memory")

// mma.sync m16n8k16 fp16 -> f32 accum
#define MMAH(C, A, B0, B1) \
    asm volatile( \
        "mma.sync.aligned.m16n8k16.row.col.f32.f16.f16.f32 " \
        "{%0,%1,%2,%3}, {%4,%5,%6,%7}, {%8,%9}, {%0,%1,%2,%3};" \
        : "+f"((C)[0]), "+f"((C)[1]), "+f"((C)[2]), "+f"((C)[3]) \
        : "r"((A)[0]), "r"((A)[1]), "r"((A)[2]), "r"((A)[3]), \
          "r"(B0), "r"(B1))

#define LDSM4(R, addr) \
    asm volatile("ldmatrix.sync.aligned.m8n8.x4.shared.b16 {%0,%1,%2,%3}, [%4];" \
        : "=r"((R)[0]), "=r"((R)[1]), "=r"((R)[2]), "=r"((R)[3]) : "r"(addr))

__device__ __forceinline__ float ex2(float x) {
    float r;
    asm("ex2.approx.f32 %0, %1;" : "=f"(r) : "f"(x));
    return r;
}

__device__ __forceinline__ uint32_t pack_h2(float a, float b) {
    __half2 t = __floats2half2_rn(a, b);
    return *(uint32_t*)&t;
}

// ---------------------------------------------------------------------------
// Kernel 0: presplit — x -> fp16 hi/lo; W's -> transposed fp16 hi/lo.
// ---------------------------------------------------------------------------
__global__ void presplit_kernel(
    const float* __restrict__ x,
    const float* __restrict__ Wt,
    const float* __restrict__ Wp,
    const float* __restrict__ Wg,
    const float* __restrict__ Wf)
{
    const int NX = Bb * Nn * Cc / 4;
    int idx = blockIdx.x * blockDim.x + threadIdx.x;
    if (idx < NX) {
        float4 v = ((const float4*)x)[idx];
        __half2 h01 = __floats2half2_rn(v.x, v.y);
        __half2 h23 = __floats2half2_rn(v.z, v.w);
        __half2 l01 = __floats2half2_rn(v.x - __half2float(h01.x),
                                        v.y - __half2float(h01.y));
        __half2 l23 = __floats2half2_rn(v.z - __half2float(h23.x),
                                        v.w - __half2float(h23.y));
        size_t o = (size_t)idx * 4;
        *(__half2*)(g_x_hi + o)     = h01;
        *(__half2*)(g_x_hi + o + 2) = h23;
        *(__half2*)(g_x_lo + o)     = l01;
        *(__half2*)(g_x_lo + o + 2) = l23;
        return;
    }
    int t = idx - NX;
    if (t < 3 * Cc * Dd) {
        int z = t / (Cc * Dd);
        int r = t % (Cc * Dd);
        int k = r / Dd, n = r % Dd;
        const float* W = (z == 0) ? Wt : (z == 1) ? Wp : Wg;
        float v = W[k * Dd + n];
        __half h = __float2half_rn(v);
        __half l = __float2half_rn(v - __half2float(h));
        g_wT_hi[(size_t)z * Dd * Cc + (size_t)n * Cc + k] = h;
        g_wT_lo[(size_t)z * Dd * Cc + (size_t)n * Cc + k] = l;
        return;
    }
    t -= 3 * Cc * Dd;
    if (t < Dd * Cc) {
        int k = t / Cc, n = t % Cc;
        float v = Wf[k * Cc + n];
        __half h = __float2half_rn(v);
        __half l = __float2half_rn(v - __half2float(h));
        g_wfT_hi[(size_t)n * Dd + k] = h;
        g_wfT_lo[(size_t)n * Dd + k] = l;
    }
}

// ---------------------------------------------------------------------------
// Kernel 1: proj_mma. out[16384,128] = x[16384,256] @ W, fp16 3-term mma.
// ---------------------------------------------------------------------------
static constexpr uint32_t PJ_XH = 0;          // 128 x 144B = 18432
static constexpr uint32_t PJ_XL = 18432;
static constexpr uint32_t PJ_WH = 36864;
static constexpr uint32_t PJ_WL = 55296;
static constexpr uint32_t PJ_BUF = 73728;
static constexpr uint32_t PJ_BYTES = 147456;

__global__ __launch_bounds__(256) void proj_mma()
{
    extern __shared__ char smem[];
    const uint32_t sb = smem_to_u32(smem);
    const int tid = threadIdx.x;
    const int warp = tid >> 5, lane = tid & 31;
    const int grp = lane >> 2, tg = lane & 3;
    const int m0 = blockIdx.x * 128;
    const int z  = blockIdx.y;

    const __half* xh = g_x_hi + (size_t)m0 * Cc;
    const __half* xl = g_x_lo + (size_t)m0 * Cc;
    const __half* wh = g_wT_hi + (size_t)z * Dd * Cc;
    const __half* wl = g_wT_lo + (size_t)z * Dd * Cc;
    float* out = (z == 0) ? g_theta : (z == 1) ? g_phi : g_g;

    auto load_chunk = [&](int buf, int ch) {
        uint32_t bb = sb + (uint32_t)buf * PJ_BUF;
        #pragma unroll
        for (int it = 0; it < 4; it++) {
            int idx = tid + it * 256;
            int c = idx & 7, row = idx >> 3;
            uint32_t d = (uint32_t)row * 144u + (uint32_t)c * 16u;
            size_t s = (size_t)row * Cc + ch * 64 + 8 * c;
            CP_ASYNC16(bb + PJ_XH + d, xh + s);
            CP_ASYNC16(bb + PJ_XL + d, xl + s);
            CP_ASYNC16(bb + PJ_WH + d, wh + s);
            CP_ASYNC16(bb + PJ_WL + d, wl + s);
        }
    };

    load_chunk(0, 0);
    CP_COMMIT();

    float O[16][4];
    #pragma unroll
    for (int i = 0; i < 16; i++)
        #pragma unroll
        for (int j = 0; j < 4; j++) O[i][j] = 0.f;

    const uint32_t a_lane = (uint32_t)(warp * 16 + (lane & 15)) * 144u
                          + (uint32_t)((lane >> 4) & 1) * 16u;
    const uint32_t b_lane = (uint32_t)((lane & 7) + ((lane & 16) ? 8 : 0)) * 144u
                          + (uint32_t)((lane & 8) ? 16 : 0);

    for (int ch = 0; ch < 4; ch++) {
        if (ch < 3) {
            load_chunk((ch + 1) & 1, ch + 1);
            CP_COMMIT();
            CP_WAIT1();
        } else {
            CP_WAIT0();
        }
        __syncthreads();
        uint32_t bb = sb + (uint32_t)(ch & 1) * PJ_BUF;
        #pragma unroll
        for (int kc = 0; kc < 4; kc++) {
            uint32_t ah[4], al[4];
            LDSM4(ah, bb + PJ_XH + a_lane + (uint32_t)kc * 32u);
            LDSM4(al, bb + PJ_XL + a_lane + (uint32_t)kc * 32u);
            #pragma unroll
            for (int j = 0; j < 8; j++) {
                uint32_t bh[4], bl[4];
                uint32_t ba = bb + b_lane + (uint32_t)j * (16u * 144u) + (uint32_t)kc * 32u;
                LDSM4(bh, ba + PJ_WH);
                LDSM4(bl, ba + PJ_WL);
                MMAH(O[2 * j],     ah, bh[0], bh[1]);
                MMAH(O[2 * j + 1], ah, bh[2], bh[3]);
                MMAH(O[2 * j],     ah, bl[0], bl[1]);
                MMAH(O[2 * j + 1], ah, bl[2], bl[3]);
                MMAH(O[2 * j],     al, bh[0], bh[1]);
                MMAH(O[2 * j + 1], al, bh[2], bh[3]);
            }
        }
        __syncthreads();
    }

    const int r0 = m0 + warp * 16 + grp;
    #pragma unroll
    for (int nb = 0; nb < 16; nb++) {
        int col = nb * 8 + tg * 2;
        *(float2*)(out + (size_t)r0 * Dd + col)       = make_float2(O[nb][0], O[nb][1]);
        *(float2*)(out + (size_t)(r0 + 8) * Dd + col) = make_float2(O[nb][2], O[nb][3]);
    }
}

// ---------------------------------------------------------------------------
// Kernel 2: maxpool(2,1) on phi + split to fp16 hi/lo, padded (row 4095 = 0).
// ---------------------------------------------------------------------------
__global__ void phisplit_kernel()
{
    int idx = blockIdx.x * blockDim.x + threadIdx.x;   // float4 index
    if (idx >= Bb * Nn * (Dd / 4)) return;
    int d4 = idx & 31;
    int rem = idx >> 5;
    int i = rem & (Nn - 1);
    int b = rem >> 12;

    float4 v = make_float4(0.f, 0.f, 0.f, 0.f);
    if (i < Mm) {
        const float* p = g_phi + ((size_t)b * Nn + i) * Dd + 4 * d4;
        float4 a = *(const float4*)p;
        float4 c = *(const float4*)(p + Dd);
        v = make_float4(fmaxf(a.x, c.x), fmaxf(a.y, c.y), fmaxf(a.z, c.z), fmaxf(a.w, c.w));
    }
    __half2 h01 = __floats2half2_rn(v.x, v.y);
    __half2 h23 = __floats2half2_rn(v.z, v.w);
    __half2 l01 = __floats2half2_rn(v.x - __half2float(h01.x),
                                    v.y - __half2float(h01.y));
    __half2 l23 = __floats2half2_rn(v.z - __half2float(h23.x),
                                    v.w - __half2float(h23.y));
    size_t dst = ((size_t)b * Nn + i) * Dd + 4 * d4;
    *(__half2*)(g_ph_hi + dst)     = h01;
    *(__half2*)(g_ph_hi + dst + 2) = h23;
    *(__half2*)(g_ph_lo + dst)     = l01;
    *(__half2*)(g_ph_lo + dst + 2) = l23;
}

// ---------------------------------------------------------------------------
// Kernel 3: maxpool(2,1) on g + TRANSPOSE to [b][d][key] + split fp16 hi/lo.
// ---------------------------------------------------------------------------
__global__ __launch_bounds__(256) void gtrans_kernel()
{
    __shared__ float tile[64 * 129];
    const int b = blockIdx.y;
    const int kb = blockIdx.x;       // 32 key blocks of 128
    const int dh = blockIdx.z;       // d half
    const int tid = threadIdx.x;
    const float* gB = g_g + (size_t)b * Nn * Dd;

    #pragma unroll
    for (int it = 0; it < 8; it++) {
        int idx = tid + it * 256;
        int d4 = idx & 15, k = idx >> 4;
        int kg = kb * 128 + k;
        float4 v = make_float4(0.f, 0.f, 0.f, 0.f);
        if (kg < Mm) {
            const float* p = gB + (size_t)kg * Dd + dh * 64 + 4 * d4;
            float4 a = *(const float4*)p;
            float4 c = *(const float4*)(p + Dd);
            v = make_float4(fmaxf(a.x, c.x), fmaxf(a.y, c.y),
                            fmaxf(a.z, c.z), fmaxf(a.w, c.w));
        }
        tile[(4 * d4 + 0) * 129 + k] = v.x;
        tile[(4 * d4 + 1) * 129 + k] = v.y;
        tile[(4 * d4 + 2) * 129 + k] = v.z;
        tile[(4 * d4 + 3) * 129 + k] = v.w;
    }
    __syncthreads();
    #pragma unroll
    for (int it = 0; it < 8; it++) {
        int idx = tid + it * 256;
        int kq = idx & 31, dl = idx >> 5;
        float v0 = tile[dl * 129 + 4 * kq + 0];
        float v1 = tile[dl * 129 + 4 * kq + 1];
        float v2 = tile[dl * 129 + 4 * kq + 2];
        float v3 = tile[dl * 129 + 4 * kq + 3];
        __half2 h01 = __floats2half2_rn(v0, v1);
        __half2 h23 = __floats2half2_rn(v2, v3);
        __half2 l01 = __floats2half2_rn(v0 - __half2float(h01.x),
                                        v1 - __half2float(h01.y));
        __half2 l23 = __floats2half2_rn(v2 - __half2float(h23.x),
                                        v3 - __half2float(h23.y));
        size_t dst = ((size_t)b * Dd + dh * 64 + dl) * (size_t)Nn + kb * 128 + 4 * kq;
        *(__half2*)(g_gT_hi + dst)     = h01;
        *(__half2*)(g_gT_hi + dst + 2) = h23;
        *(__half2*)(g_gT_lo + dst)     = l01;
        *(__half2*)(g_gT_lo + dst + 2) = l23;
    }
}

// ---------------------------------------------------------------------------
// Kernel 4: flash attention, 2-D warp tiling to cut smem crossbar traffic.
// 8 warps = 4 q-groups x 2 halves. QK: warp = 32q x 32keys (B reads halved).
// PV: warp = 32q x 64d via P staged in smem (B reads halved).
// Cross-warp row max / row sum exchanged through Ps row padding.
// QK 3-term fp16 split, PV 2-term, online row-max exp2 softmax (as R10).
// ---------------------------------------------------------------------------
static constexpr uint32_t SM_TH_HI = 0;        // 128 x 272 = 34816
static constexpr uint32_t SM_TH_LO = 34816;
static constexpr uint32_t SM_PS    = 69632;    // P: 128 rows x 144B (64 keys + pad)
                                               // red lives in pad bytes [128..135] of each row
static constexpr uint32_t SM_TILE  = 88064;    // 2 buffers x 71680
static constexpr uint32_t TILE_BUF = 71680;    // ph(34816) + gt(36864)
static constexpr uint32_t PH_LO    = 17408;
static constexpr uint32_t GT_OFF   = 34816;
static constexpr uint32_t GT_LO    = 18432;
static constexpr uint32_t SM_ATT_BYTES = 231424;

static constexpr float LOG2E = 1.4426950408889634f;

__device__ __forceinline__ void load_tile(uint32_t sb, int t, int buf, int b, int tid)
{
    const int k0 = t * 64;
    const __half* phH = g_ph_hi + ((size_t)b * Nn + k0) * Dd;
    const __half* phL = g_ph_lo + ((size_t)b * Nn + k0) * Dd;
    const __half* gtH = g_gT_hi + (size_t)b * Dd * Nn + k0;
    const __half* gtL = g_gT_lo + (size_t)b * Dd * Nn + k0;

    uint32_t phb = sb + SM_TILE + (uint32_t)buf * TILE_BUF;
    uint32_t gtb = phb + GT_OFF;

    #pragma unroll
    for (int it = 0; it < 4; it++) {
        int idx = tid + it * 256;
        int c = idx & 15, row = idx >> 4;
        uint32_t dst = phb + (uint32_t)row * 272u + (uint32_t)c * 16u;
        CP_ASYNC16(dst,          phH + (size_t)row * Dd + 8 * c);
        CP_ASYNC16(dst + PH_LO,  phL + (size_t)row * Dd + 8 * c);
    }
    #pragma unroll
    for (int it = 0; it < 4; it++) {
        int idx = tid + it * 256;
        int c = idx & 7, row = idx >> 3;
        uint32_t dst = gtb + (uint32_t)row * 144u + (uint32_t)c * 16u;
        CP_ASYNC16(dst,          gtH + (size_t)row * Nn + 8 * c);
        CP_ASYNC16(dst + GT_LO,  gtL + (size_t)row * Nn + 8 * c);
    }
}

__global__ __launch_bounds__(256, 1) void attn_kernel()
{
    extern __shared__ char smem[];
    const uint32_t sb = smem_to_u32(smem);
    const int tid = threadIdx.x;
    const int warp = tid >> 5, lane = tid & 31;
    const int grp = lane >> 2, tg = lane & 3;
    const int qg = warp >> 1, hf = warp & 1;
    const int b = blockIdx.y;
    const int q0 = blockIdx.x * 128;

    // ---- load theta [128 q][128 d] * log2(e), split fp16 hi/lo into SMEM ----
    {
        const float* thetaB = g_theta + ((size_t)b * Nn + q0) * Dd;
        #pragma unroll
        for (int it = 0; it < 16; it++) {
            int idx = tid + it * 256;
            int d4 = idx & 31, q = idx >> 5;
            float4 v = *(const float4*)(thetaB + (size_t)q * Dd + 4 * d4);
            v.x *= LOG2E; v.y *= LOG2E; v.z *= LOG2E; v.w *= LOG2E;
            __half2 h01 = __floats2half2_rn(v.x, v.y);
            __half2 h23 = __floats2half2_rn(v.z, v.w);
            __half2 l01 = __floats2half2_rn(v.x - __half2float(h01.x),
                                            v.y - __half2float(h01.y));
            __half2 l23 = __floats2half2_rn(v.z - __half2float(h23.x),
                                            v.w - __half2float(h23.y));
            uint32_t off = (uint32_t)q * 272u + (uint32_t)d4 * 8u;
            *(__half2*)(smem + SM_TH_HI + off)     = h01;
            *(__half2*)(smem + SM_TH_HI + off + 4) = h23;
            *(__half2*)(smem + SM_TH_LO + off)     = l01;
            *(__half2*)(smem + SM_TH_LO + off + 4) = l23;
        }
    }

    load_tile(sb, 0, 0, b, tid);
    CP_COMMIT();

    float O[16][4];          // [mf*8+nbd][c]: rows qg*32+mf*16+grp(+8), cols hf*64+nbd*8+tg*2
    #pragma unroll
    for (int i = 0; i < 16; i++)
        #pragma unroll
        for (int j = 0; j < 4; j++) O[i][j] = 0.f;
    float mrun[2][2] = {{-1e30f, -1e30f}, {-1e30f, -1e30f}};
    float ls[2][2]   = {{0.f, 0.f}, {0.f, 0.f}};

    const uint32_t a_th = (uint32_t)(qg * 32 + (lane & 15)) * 272u
                        + (uint32_t)((lane >> 4) & 1) * 16u;
    const uint32_t a_ps = sb + SM_PS + (uint32_t)(qg * 32 + (lane & 15)) * 144u
                        + (uint32_t)((lane >> 4) & 1) * 16u;
    const uint32_t b_ph = (uint32_t)(hf * 32 + (lane & 7) + ((lane & 16) ? 8 : 0)) * 272u
                        + (uint32_t)((lane & 8) ? 16 : 0);
    const uint32_t b_gt = (uint32_t)(hf * 64 + (lane & 7) + ((lane & 16) ? 8 : 0)) * 144u
                        + (uint32_t)((lane & 8) ? 16 : 0);

    for (int t = 0; t < 64; t++) {
        if (t < 63) {
            load_tile(sb, t + 1, (t + 1) & 1, b, tid);
            CP_COMMIT();
            CP_WAIT1();
        } else {
            CP_WAIT0();
        }
        __syncthreads();

        const uint32_t phb = sb + SM_TILE + (uint32_t)(t & 1) * TILE_BUF;
        const uint32_t gtb = phb + GT_OFF;

        // ---- QK: warp (qg, hf) computes S[32q x 32keys], 3-term split --------
        float S[2][4][4];
        #pragma unroll
        for (int mf = 0; mf < 2; mf++)
            #pragma unroll
            for (int jn = 0; jn < 4; jn++)
                #pragma unroll
                for (int c = 0; c < 4; c++) S[mf][jn][c] = 0.f;

        #pragma unroll
        for (int kc = 0; kc < 8; kc++) {
            uint32_t ah0[4], ah1[4], al0[4], al1[4];
            LDSM4(ah0, sb + SM_TH_HI + a_th + (uint32_t)kc * 32u);
            LDSM4(ah1, sb + SM_TH_HI + a_th + 16u * 272u + (uint32_t)kc * 32u);
            LDSM4(al0, sb + SM_TH_LO + a_th + (uint32_t)kc * 32u);
            LDSM4(al1, sb + SM_TH_LO + a_th + 16u * 272u + (uint32_t)kc * 32u);
            #pragma unroll
            for (int j = 0; j < 2; j++) {
                uint32_t bh[4], bl[4];
                uint32_t ba = phb + b_ph + (uint32_t)j * (16u * 272u) + (uint32_t)kc * 32u;
                LDSM4(bh, ba);
                LDSM4(bl, ba + PH_LO);
                MMAH(S[0][2 * j],     ah0, bh[0], bh[1]);
                MMAH(S[0][2 * j + 1], ah0, bh[2], bh[3]);
                MMAH(S[1][2 * j],     ah1, bh[0], bh[1]);
                MMAH(S[1][2 * j + 1], ah1, bh[2], bh[3]);
                MMAH(S[0][2 * j],     ah0, bl[0], bl[1]);
                MMAH(S[0][2 * j + 1], ah0, bl[2], bl[3]);
                MMAH(S[1][2 * j],     ah1, bl[0], bl[1]);
                MMAH(S[1][2 * j + 1], ah1, bl[2], bl[3]);
                MMAH(S[0][2 * j],     al0, bh[0], bh[1]);
                MMAH(S[0][2 * j + 1], al0, bh[2], bh[3]);
                MMAH(S[1][2 * j],     al1, bh[0], bh[1]);
                MMAH(S[1][2 * j + 1], al1, bh[2], bh[3]);
            }
        }

        // ---- softmax with cross-warp (key-half) exchange --------------------
        // partial row max over this warp's 32 keys
        float tm[2][2];
        #pragma unroll
        for (int mf = 0; mf < 2; mf++) {
            float a0 = -1e30f, a1 = -1e30f;
            #pragma unroll
            for (int jn = 0; jn < 4; jn++) {
                a0 = fmaxf(a0, fmaxf(S[mf][jn][0], S[mf][jn][1]));
                a1 = fmaxf(a1, fmaxf(S[mf][jn][2], S[mf][jn][3]));
            }
            tm[mf][0] = a0; tm[mf][1] = a1;
        }
        #pragma unroll
        for (int mf = 0; mf < 2; mf++)
            #pragma unroll
            for (int h = 0; h < 2; h++) {
                tm[mf][h] = fmaxf(tm[mf][h], __shfl_xor_sync(0xffffffffu, tm[mf][h], 1));
                tm[mf][h] = fmaxf(tm[mf][h], __shfl_xor_sync(0xffffffffu, tm[mf][h], 2));
            }
        if (tg == 0) {
            #pragma unroll
            for (int mf = 0; mf < 2; mf++)
                #pragma unroll
                for (int h = 0; h < 2; h++) {
                    int row = qg * 32 + mf * 16 + grp + 8 * h;
                    *(float*)(smem + SM_PS + (uint32_t)row * 144u + 128u + (uint32_t)hf * 4u) = tm[mf][h];
                }
        }
        __syncthreads();

        // combined max, rescale factors
        float mn[2][2], alx[2][2];
        #pragma unroll
        for (int mf = 0; mf < 2; mf++)
            #pragma unroll
            for (int h = 0; h < 2; h++) {
                int row = qg * 32 + mf * 16 + grp + 8 * h;
                float r0 = *(const float*)(smem + SM_PS + (uint32_t)row * 144u + 128u);
                float r1 = *(const float*)(smem + SM_PS + (uint32_t)row * 144u + 132u);
                float mt = fmaxf(r0, r1);
                mn[mf][h]  = fmaxf(mrun[mf][h], mt);
                alx[mf][h] = ex2(mrun[mf][h] - mn[mf][h]);
                mrun[mf][h] = mn[mf][h];
            }

        // P = 2^(s - mn), partial row sums, store P to smem
        float rs[2][2] = {{0.f, 0.f}, {0.f, 0.f}};
        #pragma unroll
        for (int mf = 0; mf < 2; mf++)
            #pragma unroll
            for (int jn = 0; jn < 4; jn++) {
                float p0 = ex2(S[mf][jn][0] - mn[mf][0]);
                float p1 = ex2(S[mf][jn][1] - mn[mf][0]);
                float p2 = ex2(S[mf][jn][2] - mn[mf][1]);
                float p3 = ex2(S[mf][jn][3] - mn[mf][1]);
                rs[mf][0] += p0 + p1;
                rs[mf][1] += p2 + p3;
                uint32_t col = (uint32_t)(hf * 32 + jn * 8 + tg * 2) * 2u;
                uint32_t r0a = sb + SM_PS + (uint32_t)(qg * 32 + mf * 16 + grp) * 144u + col;
                *(uint32_t*)(smem + (r0a - sb))            = pack_h2(p0, p1);
                *(uint32_t*)(smem + (r0a - sb) + 8u * 144u) = pack_h2(p2, p3);
            }
        #pragma unroll
        for (int mf = 0; mf < 2; mf++)
            #pragma unroll
            for (int h = 0; h < 2; h++) {
                rs[mf][h] += __shfl_xor_sync(0xffffffffu, rs[mf][h], 1);
                rs[mf][h] += __shfl_xor_sync(0xffffffffu, rs[mf][h], 2);
            }
        // rescale O while waiting
        #pragma unroll
        for (int i = 0; i < 16; i++) {
            int mf = i >> 3;
            O[i][0] *= alx[mf][0]; O[i][1] *= alx[mf][0];
            O[i][2] *= alx[mf][1]; O[i][3] *= alx[mf][1];
        }
        __syncthreads();   // Ps visible; red max-reads done

        if (tg == 0) {
            #pragma unroll
            for (int mf = 0; mf < 2; mf++)
                #pragma unroll
                for (int h = 0; h < 2; h++) {
                    int row = qg * 32 + mf * 16 + grp + 8 * h;
                    *(float*)(smem + SM_PS + (uint32_t)row * 144u + 128u + (uint32_t)hf * 4u) = rs[mf][h];
                }
        }
        __syncthreads();

        #pragma unroll
        for (int mf = 0; mf < 2; mf++)
            #pragma unroll
            for (int h = 0; h < 2; h++) {
                int row = qg * 32 + mf * 16 + grp + 8 * h;
                float r0 = *(const float*)(smem + SM_PS + (uint32_t)row * 144u + 128u);
                float r1 = *(const float*)(smem + SM_PS + (uint32_t)row * 144u + 132u);
                ls[mf][h] = ls[mf][h] * alx[mf][h] + r0 + r1;
            }

        // ---- PV: warp (qg, hf) computes O[32q x 64d], P from smem -----------
        #pragma unroll
        for (int kc = 0; kc < 4; kc++) {
            uint32_t pa0[4], pa1[4];
            LDSM4(pa0, a_ps + (uint32_t)kc * 32u);
            LDSM4(pa1, a_ps + 16u * 144u + (uint32_t)kc * 32u);
            #pragma unroll
            for (int jd = 0; jd < 4; jd++) {
                uint32_t bh[4], bl[4];
                uint32_t ba = gtb + b_gt + (uint32_t)jd * (16u * 144u) + (uint32_t)kc * 32u;
                LDSM4(bh, ba);
                LDSM4(bl, ba + GT_LO);
                MMAH(O[0 * 8 + 2 * jd],     pa0, bh[0], bh[1]);
                MMAH(O[0 * 8 + 2 * jd + 1], pa0, bh[2], bh[3]);
                MMAH(O[1 * 8 + 2 * jd],     pa1, bh[0], bh[1]);
                MMAH(O[1 * 8 + 2 * jd + 1], pa1, bh[2], bh[3]);
                MMAH(O[0 * 8 + 2 * jd],     pa0, bl[0], bl[1]);
                MMAH(O[0 * 8 + 2 * jd + 1], pa0, bl[2], bl[3]);
                MMAH(O[1 * 8 + 2 * jd],     pa1, bl[0], bl[1]);
                MMAH(O[1 * 8 + 2 * jd + 1], pa1, bl[2], bl[3]);
            }
        }
        __syncthreads();   // all reads done before next prefetch / next P store
    }

    // ---- epilogue: y = O / l, written as fp16 hi/lo -------------------------
    float inv[2][2];
    #pragma unroll
    for (int mf = 0; mf < 2; mf++)
        #pragma unroll
        for (int h = 0; h < 2; h++) inv[mf][h] = 1.f / ls[mf][h];

    #pragma unroll
    for (int i = 0; i < 16; i++) {
        int mf = i >> 3, nbd = i & 7;
        int r0 = q0 + qg * 32 + mf * 16 + grp;
        int col = hf * 64 + nbd * 8 + tg * 2;
        size_t o0 = ((size_t)b * Nn + r0) * Dd + col;
        size_t o1 = ((size_t)b * Nn + r0 + 8) * Dd + col;
        float y0 = O[i][0] * inv[mf][0], y1 = O[i][1] * inv[mf][0];
        float y2 = O[i][2] * inv[mf][1], y3 = O[i][3] * inv[mf][1];
        __half2 h01 = __floats2half2_rn(y0, y1);
        __half2 h23 = __floats2half2_rn(y2, y3);
        __half2 l01 = __floats2half2_rn(y0 - __half2float(h01.x),
                                        y1 - __half2float(h01.y));
        __half2 l23 = __floats2half2_rn(y2 - __half2float(h23.x),
                                        y3 - __half2float(h23.y));
        *(__half2*)(g_y_hi + o0) = h01;
        *(__half2*)(g_y_lo + o0) = l01;
        *(__half2*)(g_y_hi + o1) = h23;
        *(__half2*)(g_y_lo + o1) = l23;
    }
}

// ---------------------------------------------------------------------------
// Kernel 5: final_mma. z = x + y @ Wf via fp16 3-term mma. K=128 single load.
// ---------------------------------------------------------------------------
static constexpr uint32_t FN_YH = 0;          // 128 x 272B = 34816
static constexpr uint32_t FN_YL = 34816;
static constexpr uint32_t FN_FH = 69632;
static constexpr uint32_t FN_FL = 104448;
static constexpr uint32_t FN_BYTES = 139264;

__global__ __launch_bounds__(256) void final_mma(
    const float* __restrict__ x,
    float* __restrict__ out)
{
    extern __shared__ char smem[];
    const uint32_t sb = smem_to_u32(smem);
    const int tid = threadIdx.x;
    const int warp = tid >> 5, lane = tid & 31;
    const int grp = lane >> 2, tg = lane & 3;
    const int m0 = blockIdx.y * 128;
    const int n0 = blockIdx.x * 128;

    #pragma unroll
    for (int it = 0; it < 8; it++) {
        int idx = tid + it * 256;
        int c = idx & 15, row = idx >> 4;
        uint32_t d = (uint32_t)row * 272u + (uint32_t)c * 16u;
        CP_ASYNC16(sb + FN_YH + d, g_y_hi + (size_t)(m0 + row) * Dd + 8 * c);
        CP_ASYNC16(sb + FN_YL + d, g_y_lo + (size_t)(m0 + row) * Dd + 8 * c);
        CP_ASYNC16(sb + FN_FH + d, g_wfT_hi + (size_t)(n0 + row) * Dd + 8 * c);
        CP_ASYNC16(sb + FN_FL + d, g_wfT_lo + (size_t)(n0 + row) * Dd + 8 * c);
    }
    CP_COMMIT();
    CP_WAIT0();
    __syncthreads();

    float O[16][4];
    #pragma unroll
    for (int i = 0; i < 16; i++)
        #pragma unroll
        for (int j = 0; j < 4; j++) O[i][j] = 0.f;

    const uint32_t a_lane = (uint32_t)(warp * 16 + (lane & 15)) * 272u
                          + (uint32_t)((lane >> 4) & 1) * 16u;
    const uint32_t b_lane = (uint32_t)((lane & 7) + ((lane & 16) ? 8 : 0)) * 272u
                          + (uint32_t)((lane & 8) ? 16 : 0);

    #pragma unroll
    for (int kc = 0; kc < 8; kc++) {
        uint32_t ah[4], al[4];
        LDSM4(ah, sb + FN_YH + a_lane + (uint32_t)kc * 32u);
        LDSM4(al, sb + FN_YL + a_lane + (uint32_t)kc * 32u);
        #pragma unroll
        for (int j = 0; j < 8; j++) {
            uint32_t bh[4], bl[4];
            uint32_t ba = sb + b_lane + (uint32_t)j * (16u * 272u) + (uint32_t)kc * 32u;
            LDSM4(bh, ba + FN_FH);
            LDSM4(bl, ba + FN_FL);
            MMAH(O[2 * j],     ah, bh[0], bh[1]);
            MMAH(O[2 * j + 1], ah, bh[2], bh[3]);
            MMAH(O[2 * j],     ah, bl[0], bl[1]);
            MMAH(O[2 * j + 1], ah, bl[2], bl[3]);
            MMAH(O[2 * j],     al, bh[0], bh[1]);
            MMAH(O[2 * j + 1], al, bh[2], bh[3]);
        }
    }

    const int r0 = m0 + warp * 16 + grp;
    #pragma unroll
    for (int nb = 0; nb < 16; nb++) {
        int col = n0 + nb * 8 + tg * 2;
        size_t o0 = (size_t)r0 * Cc + col;
        size_t o1 = (size_t)(r0 + 8) * Cc + col;
        float2 x0 = *(const float2*)(x + o0);
        float2 x1 = *(const float2*)(x + o1);
        *(float2*)(out + o0) = make_float2(O[nb][0] + x0.x, O[nb][1] + x0.y);
        *(float2*)(out + o1) = make_float2(O[nb][2] + x1.x, O[nb][3] + x1.y);
    }
}

// ---------------------------------------------------------------------------
extern "C" void kernel_launch(void* const* d_in, const int* in_sizes, int n_in,
                              void* d_out, int out_size)
{
    const float* x  = (const float*)d_in[0];
    const float* Wt = (const float*)d_in[1];
    const float* Wp = (const float*)d_in[2];
    const float* Wg = (const float*)d_in[3];
    const float* Wf = (const float*)d_in[4];
    float* out = (float*)d_out;

    cudaFuncSetAttribute(attn_kernel, cudaFuncAttributeMaxDynamicSharedMemorySize, SM_ATT_BYTES);
    cudaFuncSetAttribute(proj_mma,    cudaFuncAttributeMaxDynamicSharedMemorySize, PJ_BYTES);
    cudaFuncSetAttribute(final_mma,   cudaFuncAttributeMaxDynamicSharedMemorySize, FN_BYTES);

    // 0) presplit x and weights
    {
        int total = Bb * Nn * Cc / 4 + 3 * Cc * Dd + Dd * Cc;
        presplit_kernel<<<(total + 255) / 256, 256>>>(x, Wt, Wp, Wg, Wf);
    }

    // 1) projections via tensor cores
    proj_mma<<<dim3(128, 3), 256, PJ_BYTES>>>();

    // 2) phi pool + fp16 split
    {
        int total = Bb * Nn * (Dd / 4);
        phisplit_kernel<<<(total + 255) / 256, 256>>>();
    }

    // 3) g pool + transpose + fp16 split
    gtrans_kernel<<<dim3(32, 4, 2), 256>>>();

    // 4) warp-MMA flash attention (2-D warp tiling, P via smem)
    attn_kernel<<<dim3(32, 4), 256, SM_ATT_BYTES>>>();

    // 5) final projection + residual via tensor cores
    final_mma<<<dim3(2, 128), 256, FN_BYTES>>>(x, out);
}

// round 16
// speedup vs baseline: 1.0710x; 1.0710x over previous
#include <cuda_runtime.h>
#include <cuda_fp16.h>
#include <cstdint>

// Problem constants
static constexpr int Bb = 4;
static constexpr int Cc = 256;
static constexpr int Dd = 128;
static constexpr int Nn = 4096;
static constexpr int Mm = Nn - 1;    // 4095

// Scratch (device globals; no runtime allocation allowed)
__device__ float g_theta[Bb * Nn * Dd];
__device__ float g_phi  [Bb * Nn * Dd];
__device__ float g_g    [Bb * Nn * Dd];
// x split to fp16 hi/lo [16384][256]
__device__ __half g_x_hi[Bb * Nn * Cc];
__device__ __half g_x_lo[Bb * Nn * Cc];
// Wt/Wp/Wg transposed [z][n=128][k=256], split hi/lo
__device__ __half g_wT_hi[3 * Dd * Cc];
__device__ __half g_wT_lo[3 * Dd * Cc];
// Wf transposed [n=256][k=128], split hi/lo
__device__ __half g_wfT_hi[Cc * Dd];
__device__ __half g_wfT_lo[Cc * Dd];
// y (attention output) split fp16 hi/lo [16384][128]
__device__ __half g_y_hi[Bb * Nn * Dd];
__device__ __half g_y_lo[Bb * Nn * Dd];
// pooled phi, split to fp16 hi/lo, padded to 4096 rows (row 4095 = 0)
__device__ __half g_ph_hi[Bb * Nn * Dd];
__device__ __half g_ph_lo[Bb * Nn * Dd];
// pooled g, TRANSPOSED [b][d=128][key=4096], split hi/lo, key 4095 = 0
__device__ __half g_gT_hi[Bb * Dd * Nn];
__device__ __half g_gT_lo[Bb * Dd * Nn];

// ===========================================================================
// Helpers
// ===========================================================================
__device__ __forceinline__ uint32_t smem_to_u32(const void* p) {
    uint32_t a;
    asm("{ .reg .u64 t; cvta.to.shared.u64 t, %1; cvt.u32.u64 %0, t; }"
        : "=r"(a) : "l"(p));
    return a;
}

#define CP_ASYNC16(dst_u32, src_ptr) \
    asm volatile("cp.async.cg.shared.global [%0], [%1], 16;" \
        :: "r"(dst_u32), "l"(src_ptr) : "memory")
#define CP_COMMIT() asm volatile("cp.async.commit_group;" ::: "memory")
#define CP_WAIT1()  asm volatile("cp.async.wait_group 1;" ::: "memory")
#define CP_WAIT0()  asm volatile("cp.async.wait_group 0;" ::: "memory")

// mma.sync m16n8k16 fp16 -> f32 accum
#define MMAH(C, A, B0, B1) \
    asm volatile( \
        "mma.sync.aligned.m16n8k16.row.col.f32.f16.f16.f32 " \
        "{%0,%1,%2,%3}, {%4,%5,%6,%7}, {%8,%9}, {%0,%1,%2,%3};" \
        : "+f"((C)[0]), "+f"((C)[1]), "+f"((C)[2]), "+f"((C)[3]) \
        : "r"((A)[0]), "r"((A)[1]), "r"((A)[2]), "r"((A)[3]), \
          "r"(B0), "r"(B1))

#define LDSM4(R, addr) \
    asm volatile("ldmatrix.sync.aligned.m8n8.x4.shared.b16 {%0,%1,%2,%3}, [%4];" \
        : "=r"((R)[0]), "=r"((R)[1]), "=r"((R)[2]), "=r"((R)[3]) : "r"(addr))

__device__ __forceinline__ float ex2(float x) {
    float r;
    asm("ex2.approx.f32 %0, %1;" : "=f"(r) : "f"(x));
    return r;
}

__device__ __forceinline__ uint32_t pack_h2(float a, float b) {
    __half2 t = __floats2half2_rn(a, b);
    return *(uint32_t*)&t;
}

// ---------------------------------------------------------------------------
// Kernel 0: presplit — x -> fp16 hi/lo; W's -> transposed fp16 hi/lo.
// ---------------------------------------------------------------------------
__global__ void presplit_kernel(
    const float* __restrict__ x,
    const float* __restrict__ Wt,
    const float* __restrict__ Wp,
    const float* __restrict__ Wg,
    const float* __restrict__ Wf)
{
    const int NX = Bb * Nn * Cc / 4;
    int idx = blockIdx.x * blockDim.x + threadIdx.x;
    if (idx < NX) {
        float4 v = ((const float4*)x)[idx];
        __half2 h01 = __floats2half2_rn(v.x, v.y);
        __half2 h23 = __floats2half2_rn(v.z, v.w);
        __half2 l01 = __floats2half2_rn(v.x - __half2float(h01.x),
                                        v.y - __half2float(h01.y));
        __half2 l23 = __floats2half2_rn(v.z - __half2float(h23.x),
                                        v.w - __half2float(h23.y));
        size_t o = (size_t)idx * 4;
        *(__half2*)(g_x_hi + o)     = h01;
        *(__half2*)(g_x_hi + o + 2) = h23;
        *(__half2*)(g_x_lo + o)     = l01;
        *(__half2*)(g_x_lo + o + 2) = l23;
        return;
    }
    int t = idx - NX;
    if (t < 3 * Cc * Dd) {
        int z = t / (Cc * Dd);
        int r = t % (Cc * Dd);
        int k = r / Dd, n = r % Dd;
        const float* W = (z == 0) ? Wt : (z == 1) ? Wp : Wg;
        float v = W[k * Dd + n];
        __half h = __float2half_rn(v);
        __half l = __float2half_rn(v - __half2float(h));
        g_wT_hi[(size_t)z * Dd * Cc + (size_t)n * Cc + k] = h;
        g_wT_lo[(size_t)z * Dd * Cc + (size_t)n * Cc + k] = l;
        return;
    }
    t -= 3 * Cc * Dd;
    if (t < Dd * Cc) {
        int k = t / Cc, n = t % Cc;
        float v = Wf[k * Cc + n];
        __half h = __float2half_rn(v);
        __half l = __float2half_rn(v - __half2float(h));
        g_wfT_hi[(size_t)n * Dd + k] = h;
        g_wfT_lo[(size_t)n * Dd + k] = l;
    }
}

// ---------------------------------------------------------------------------
// Kernel 1: proj_mma. out[16384,128] = x[16384,256] @ W, fp16 3-term mma.
// ---------------------------------------------------------------------------
static constexpr uint32_t PJ_XH = 0;          // 128 x 144B = 18432
static constexpr uint32_t PJ_XL = 18432;
static constexpr uint32_t PJ_WH = 36864;
static constexpr uint32_t PJ_WL = 55296;
static constexpr uint32_t PJ_BUF = 73728;
static constexpr uint32_t PJ_BYTES = 147456;

__global__ __launch_bounds__(256) void proj_mma()
{
    extern __shared__ char smem[];
    const uint32_t sb = smem_to_u32(smem);
    const int tid = threadIdx.x;
    const int warp = tid >> 5, lane = tid & 31;
    const int grp = lane >> 2, tg = lane & 3;
    const int m0 = blockIdx.x * 128;
    const int z  = blockIdx.y;

    const __half* xh = g_x_hi + (size_t)m0 * Cc;
    const __half* xl = g_x_lo + (size_t)m0 * Cc;
    const __half* wh = g_wT_hi + (size_t)z * Dd * Cc;
    const __half* wl = g_wT_lo + (size_t)z * Dd * Cc;
    float* out = (z == 0) ? g_theta : (z == 1) ? g_phi : g_g;

    auto load_chunk = [&](int buf, int ch) {
        uint32_t bb = sb + (uint32_t)buf * PJ_BUF;
        #pragma unroll
        for (int it = 0; it < 4; it++) {
            int idx = tid + it * 256;
            int c = idx & 7, row = idx >> 3;
            uint32_t d = (uint32_t)row * 144u + (uint32_t)c * 16u;
            size_t s = (size_t)row * Cc + ch * 64 + 8 * c;
            CP_ASYNC16(bb + PJ_XH + d, xh + s);
            CP_ASYNC16(bb + PJ_XL + d, xl + s);
            CP_ASYNC16(bb + PJ_WH + d, wh + s);
            CP_ASYNC16(bb + PJ_WL + d, wl + s);
        }
    };

    load_chunk(0, 0);
    CP_COMMIT();

    float O[16][4];
    #pragma unroll
    for (int i = 0; i < 16; i++)
        #pragma unroll
        for (int j = 0; j < 4; j++) O[i][j] = 0.f;

    const uint32_t a_lane = (uint32_t)(warp * 16 + (lane & 15)) * 144u
                          + (uint32_t)((lane >> 4) & 1) * 16u;
    const uint32_t b_lane = (uint32_t)((lane & 7) + ((lane & 16) ? 8 : 0)) * 144u
                          + (uint32_t)((lane & 8) ? 16 : 0);

    for (int ch = 0; ch < 4; ch++) {
        if (ch < 3) {
            load_chunk((ch + 1) & 1, ch + 1);
            CP_COMMIT();
            CP_WAIT1();
        } else {
            CP_WAIT0();
        }
        __syncthreads();
        uint32_t bb = sb + (uint32_t)(ch & 1) * PJ_BUF;
        #pragma unroll
        for (int kc = 0; kc < 4; kc++) {
            uint32_t ah[4], al[4];
            LDSM4(ah, bb + PJ_XH + a_lane + (uint32_t)kc * 32u);
            LDSM4(al, bb + PJ_XL + a_lane + (uint32_t)kc * 32u);
            #pragma unroll
            for (int j = 0; j < 8; j++) {
                uint32_t bh[4], bl[4];
                uint32_t ba = bb + b_lane + (uint32_t)j * (16u * 144u) + (uint32_t)kc * 32u;
                LDSM4(bh, ba + PJ_WH);
                LDSM4(bl, ba + PJ_WL);
                MMAH(O[2 * j],     ah, bh[0], bh[1]);
                MMAH(O[2 * j + 1], ah, bh[2], bh[3]);
                MMAH(O[2 * j],     ah, bl[0], bl[1]);
                MMAH(O[2 * j + 1], ah, bl[2], bl[3]);
                MMAH(O[2 * j],     al, bh[0], bh[1]);
                MMAH(O[2 * j + 1], al, bh[2], bh[3]);
            }
        }
        __syncthreads();
    }

    const int r0 = m0 + warp * 16 + grp;
    #pragma unroll
    for (int nb = 0; nb < 16; nb++) {
        int col = nb * 8 + tg * 2;
        *(float2*)(out + (size_t)r0 * Dd + col)       = make_float2(O[nb][0], O[nb][1]);
        *(float2*)(out + (size_t)(r0 + 8) * Dd + col) = make_float2(O[nb][2], O[nb][3]);
    }
}

// ---------------------------------------------------------------------------
// Kernel 2: fused pooling. blockIdx.z == 2: phi pool + split (role A,
// 128 rows per block: 32 blocks x 128 = 4096 rows). blockIdx.z in {0,1}:
// g pool + transpose + split, d-half = z (role B, 32 key-blocks of 128).
// ---------------------------------------------------------------------------
__global__ __launch_bounds__(256) void pool_kernel()
{
    const int b = blockIdx.y;
    const int tid = threadIdx.x;

    if (blockIdx.z == 2) {
        // ---- phi: maxpool(2,1) + fp16 split, rows blockIdx.x*128 .. +127 ----
        int base = blockIdx.x * 128;
        #pragma unroll
        for (int it = 0; it < 16; it++) {
            int idx = tid + it * 256;          // 128 rows x 32 float4 cols
            int d4 = idx & 31;
            int i = base + (idx >> 5);
            float4 v = make_float4(0.f, 0.f, 0.f, 0.f);
            if (i < Mm) {
                const float* p = g_phi + ((size_t)b * Nn + i) * Dd + 4 * d4;
                float4 a = *(const float4*)p;
                float4 c = *(const float4*)(p + Dd);
                v = make_float4(fmaxf(a.x, c.x), fmaxf(a.y, c.y),
                                fmaxf(a.z, c.z), fmaxf(a.w, c.w));
            }
            __half2 h01 = __floats2half2_rn(v.x, v.y);
            __half2 h23 = __floats2half2_rn(v.z, v.w);
            __half2 l01 = __floats2half2_rn(v.x - __half2float(h01.x),
                                            v.y - __half2float(h01.y));
            __half2 l23 = __floats2half2_rn(v.z - __half2float(h23.x),
                                            v.w - __half2float(h23.y));
            size_t dst = ((size_t)b * Nn + i) * Dd + 4 * d4;
            *(__half2*)(g_ph_hi + dst)     = h01;
            *(__half2*)(g_ph_hi + dst + 2) = h23;
            *(__half2*)(g_ph_lo + dst)     = l01;
            *(__half2*)(g_ph_lo + dst + 2) = l23;
        }
        return;
    }

    // ---- g: maxpool(2,1) + transpose + fp16 split -------------------------
    __shared__ float tile[64 * 129];
    const int kb = blockIdx.x;       // 32 key blocks of 128
    const int dh = blockIdx.z;       // d half (0/1)
    const float* gB = g_g + (size_t)b * Nn * Dd;

    #pragma unroll
    for (int it = 0; it < 8; it++) {
        int idx = tid + it * 256;
        int d4 = idx & 15, k = idx >> 4;
        int kg = kb * 128 + k;
        float4 v = make_float4(0.f, 0.f, 0.f, 0.f);
        if (kg < Mm) {
            const float* p = gB + (size_t)kg * Dd + dh * 64 + 4 * d4;
            float4 a = *(const float4*)p;
            float4 c = *(const float4*)(p + Dd);
            v = make_float4(fmaxf(a.x, c.x), fmaxf(a.y, c.y),
                            fmaxf(a.z, c.z), fmaxf(a.w, c.w));
        }
        tile[(4 * d4 + 0) * 129 + k] = v.x;
        tile[(4 * d4 + 1) * 129 + k] = v.y;
        tile[(4 * d4 + 2) * 129 + k] = v.z;
        tile[(4 * d4 + 3) * 129 + k] = v.w;
    }
    __syncthreads();
    #pragma unroll
    for (int it = 0; it < 8; it++) {
        int idx = tid + it * 256;
        int kq = idx & 31, dl = idx >> 5;
        float v0 = tile[dl * 129 + 4 * kq + 0];
        float v1 = tile[dl * 129 + 4 * kq + 1];
        float v2 = tile[dl * 129 + 4 * kq + 2];
        float v3 = tile[dl * 129 + 4 * kq + 3];
        __half2 h01 = __floats2half2_rn(v0, v1);
        __half2 h23 = __floats2half2_rn(v2, v3);
        __half2 l01 = __floats2half2_rn(v0 - __half2float(h01.x),
                                        v1 - __half2float(h01.y));
        __half2 l23 = __floats2half2_rn(v2 - __half2float(h23.x),
                                        v3 - __half2float(h23.y));
        size_t dst = ((size_t)b * Dd + dh * 64 + dl) * (size_t)Nn + kb * 128 + 4 * kq;
        *(__half2*)(g_gT_hi + dst)     = h01;
        *(__half2*)(g_gT_hi + dst + 2) = h23;
        *(__half2*)(g_gT_lo + dst)     = l01;
        *(__half2*)(g_gT_lo + dst + 2) = l23;
    }
}

// ---------------------------------------------------------------------------
// Kernel 4: flash attention (R10 layout — proven optimum of this family).
// 128 queries/CTA, 8 warps of 16q x 64keys, double-buffered cp.async tiles.
// QK 3-term fp16 split, PV 2-term, online row-max exp2 softmax.
// ---------------------------------------------------------------------------
static constexpr uint32_t SM_TH_HI = 0;                  // 128*272 = 34816
static constexpr uint32_t SM_TH_LO = 34816;
static constexpr uint32_t SM_PH    = 69632;              // [buf][hi/lo]: 17408 each
static constexpr uint32_t PH_BUF   = 34816;
static constexpr uint32_t PH_LO    = 17408;
static constexpr uint32_t SM_GT    = 139264;             // [buf][hi/lo]: 18432 each
static constexpr uint32_t GT_BUF   = 36864;
static constexpr uint32_t GT_LO    = 18432;
static constexpr uint32_t SM_ATT_BYTES = 212992;

static constexpr float LOG2E = 1.4426950408889634f;

__device__ __forceinline__ void load_tile(uint32_t sb, int t, int buf, int b, int tid)
{
    const int k0 = t * 64;
    const __half* phH = g_ph_hi + ((size_t)b * Nn + k0) * Dd;
    const __half* phL = g_ph_lo + ((size_t)b * Nn + k0) * Dd;
    const __half* gtH = g_gT_hi + (size_t)b * Dd * Nn + k0;
    const __half* gtL = g_gT_lo + (size_t)b * Dd * Nn + k0;

    uint32_t phb = sb + SM_PH + (uint32_t)buf * PH_BUF;
    uint32_t gtb = sb + SM_GT + (uint32_t)buf * GT_BUF;

    #pragma unroll
    for (int it = 0; it < 4; it++) {
        int idx = tid + it * 256;
        int c = idx & 15, row = idx >> 4;
        uint32_t dst = phb + (uint32_t)row * 272u + (uint32_t)c * 16u;
        CP_ASYNC16(dst,          phH + (size_t)row * Dd + 8 * c);
        CP_ASYNC16(dst + PH_LO,  phL + (size_t)row * Dd + 8 * c);
    }
    #pragma unroll
    for (int it = 0; it < 4; it++) {
        int idx = tid + it * 256;
        int c = idx & 7, row = idx >> 3;
        uint32_t dst = gtb + (uint32_t)row * 144u + (uint32_t)c * 16u;
        CP_ASYNC16(dst,          gtH + (size_t)row * Nn + 8 * c);
        CP_ASYNC16(dst + GT_LO,  gtL + (size_t)row * Nn + 8 * c);
    }
}

__global__ __launch_bounds__(256, 1) void attn_kernel()
{
    extern __shared__ char smem[];
    const uint32_t sb = smem_to_u32(smem);
    const int tid = threadIdx.x;
    const int warp = tid >> 5, lane = tid & 31;
    const int grp = lane >> 2, tg = lane & 3;
    const int b = blockIdx.y;
    const int q0 = blockIdx.x * 128;

    // ---- load theta [128 q][128 d] * log2(e), split fp16 hi/lo into SMEM ----
    {
        const float* thetaB = g_theta + ((size_t)b * Nn + q0) * Dd;
        #pragma unroll
        for (int it = 0; it < 16; it++) {
            int idx = tid + it * 256;
            int d4 = idx & 31, q = idx >> 5;
            float4 v = *(const float4*)(thetaB + (size_t)q * Dd + 4 * d4);
            v.x *= LOG2E; v.y *= LOG2E; v.z *= LOG2E; v.w *= LOG2E;
            __half2 h01 = __floats2half2_rn(v.x, v.y);
            __half2 h23 = __floats2half2_rn(v.z, v.w);
            __half2 l01 = __floats2half2_rn(v.x - __half2float(h01.x),
                                            v.y - __half2float(h01.y));
            __half2 l23 = __floats2half2_rn(v.z - __half2float(h23.x),
                                            v.w - __half2float(h23.y));
            uint32_t off = (uint32_t)q * 272u + (uint32_t)d4 * 8u;
            *(__half2*)(smem + SM_TH_HI + off)     = h01;
            *(__half2*)(smem + SM_TH_HI + off + 4) = h23;
            *(__half2*)(smem + SM_TH_LO + off)     = l01;
            *(__half2*)(smem + SM_TH_LO + off + 4) = l23;
        }
    }

    load_tile(sb, 0, 0, b, tid);
    CP_COMMIT();

    float O[16][4];
    #pragma unroll
    for (int i = 0; i < 16; i++)
        #pragma unroll
        for (int j = 0; j < 4; j++) O[i][j] = 0.f;
    float lsum0 = 0.f, lsum1 = 0.f;
    float m0 = -1e30f, m1 = -1e30f;

    const uint32_t a_lane = (uint32_t)(warp * 16 + (lane & 15)) * 272u
                          + (uint32_t)((lane >> 4) & 1) * 16u;
    const uint32_t qa_hi = sb + SM_TH_HI + a_lane;
    const uint32_t qa_lo = sb + SM_TH_LO + a_lane;
    const uint32_t b_lane_ph = (uint32_t)((lane & 7) + ((lane & 16) ? 8 : 0)) * 272u
                             + (uint32_t)((lane & 8) ? 16 : 0);
    const uint32_t b_lane_gt = (uint32_t)((lane & 7) + ((lane & 16) ? 8 : 0)) * 144u
                             + (uint32_t)((lane & 8) ? 16 : 0);

    for (int t = 0; t < 64; t++) {
        if (t < 63) {
            load_tile(sb, t + 1, (t + 1) & 1, b, tid);
            CP_COMMIT();
            CP_WAIT1();
        } else {
            CP_WAIT0();
        }
        __syncthreads();

        const uint32_t phb = sb + SM_PH + (uint32_t)(t & 1) * PH_BUF;
        const uint32_t gtb = sb + SM_GT + (uint32_t)(t & 1) * GT_BUF;

        // ---- QK: S = th_hi@ph_hi + th_hi@ph_lo + th_lo@ph_hi ----------------
        float S[8][4];
        #pragma unroll
        for (int i = 0; i < 8; i++)
            #pragma unroll
            for (int j = 0; j < 4; j++) S[i][j] = 0.f;

        #pragma unroll
        for (int kc = 0; kc < 8; kc++) {
            uint32_t ah[4], al[4];
            LDSM4(ah, qa_hi + (uint32_t)kc * 32u);
            LDSM4(al, qa_lo + (uint32_t)kc * 32u);
            #pragma unroll
            for (int j = 0; j < 4; j++) {
                uint32_t bh[4], bl[4];
                uint32_t ba = phb + b_lane_ph + (uint32_t)j * (16u * 272u) + (uint32_t)kc * 32u;
                LDSM4(bh, ba);
                LDSM4(bl, ba + PH_LO);
                MMAH(S[2 * j],     ah, bh[0], bh[1]);
                MMAH(S[2 * j + 1], ah, bh[2], bh[3]);
                MMAH(S[2 * j],     ah, bl[0], bl[1]);
                MMAH(S[2 * j + 1], ah, bl[2], bl[3]);
                MMAH(S[2 * j],     al, bh[0], bh[1]);
                MMAH(S[2 * j + 1], al, bh[2], bh[3]);
            }
        }

        // ---- online softmax: row max, rescale O/lsum, p = 2^(s - m) ---------
        float tm0 = -1e30f, tm1 = -1e30f;
        #pragma unroll
        for (int nb = 0; nb < 8; nb++) {
            tm0 = fmaxf(tm0, fmaxf(S[nb][0], S[nb][1]));
            tm1 = fmaxf(tm1, fmaxf(S[nb][2], S[nb][3]));
        }
        tm0 = fmaxf(tm0, __shfl_xor_sync(0xffffffffu, tm0, 1));
        tm0 = fmaxf(tm0, __shfl_xor_sync(0xffffffffu, tm0, 2));
        tm1 = fmaxf(tm1, __shfl_xor_sync(0xffffffffu, tm1, 1));
        tm1 = fmaxf(tm1, __shfl_xor_sync(0xffffffffu, tm1, 2));
        const float mn0 = fmaxf(m0, tm0);
        const float mn1 = fmaxf(m1, tm1);
        const float al0 = ex2(m0 - mn0);
        const float al1 = ex2(m1 - mn1);
        m0 = mn0; m1 = mn1;

        uint32_t pkh[16];
        float rs0 = 0.f, rs1 = 0.f;
        #pragma unroll
        for (int nb = 0; nb < 8; nb++) {
            float p0 = ex2(S[nb][0] - mn0);
            float p1 = ex2(S[nb][1] - mn0);
            float p2 = ex2(S[nb][2] - mn1);
            float p3 = ex2(S[nb][3] - mn1);
            rs0 += p0 + p1;
            rs1 += p2 + p3;
            pkh[2 * nb]     = pack_h2(p0, p1);
            pkh[2 * nb + 1] = pack_h2(p2, p3);
        }
        lsum0 = lsum0 * al0 + rs0;
        lsum1 = lsum1 * al1 + rs1;
        #pragma unroll
        for (int nb = 0; nb < 16; nb++) {
            O[nb][0] *= al0; O[nb][1] *= al0;
            O[nb][2] *= al1; O[nb][3] *= al1;
        }

        // ---- PV: O += P_hi@G_hi + P_hi@G_lo ---------------------------------
        #pragma unroll
        for (int kc = 0; kc < 4; kc++) {
            uint32_t ah[4] = { pkh[4 * kc], pkh[4 * kc + 1], pkh[4 * kc + 2], pkh[4 * kc + 3] };
            #pragma unroll
            for (int j = 0; j < 8; j++) {
                uint32_t bh[4], bl[4];
                uint32_t ba = gtb + b_lane_gt + (uint32_t)j * (16u * 144u) + (uint32_t)kc * 32u;
                LDSM4(bh, ba);
                LDSM4(bl, ba + GT_LO);
                MMAH(O[2 * j],     ah, bh[0], bh[1]);
                MMAH(O[2 * j + 1], ah, bh[2], bh[3]);
                MMAH(O[2 * j],     ah, bl[0], bl[1]);
                MMAH(O[2 * j + 1], ah, bl[2], bl[3]);
            }
        }
        __syncthreads();   // all reads of this buffer done before next prefetch overwrites
    }

    // ---- epilogue: y = O / l, written as fp16 hi/lo -------------------------
    lsum0 += __shfl_xor_sync(0xffffffffu, lsum0, 1);
    lsum0 += __shfl_xor_sync(0xffffffffu, lsum0, 2);
    lsum1 += __shfl_xor_sync(0xffffffffu, lsum1, 1);
    lsum1 += __shfl_xor_sync(0xffffffffu, lsum1, 2);
    const float inv0 = 1.f / lsum0;
    const float inv1 = 1.f / lsum1;

    const int r0 = q0 + warp * 16 + grp;
    #pragma unroll
    for (int nb = 0; nb < 16; nb++) {
        int col = nb * 8 + tg * 2;
        size_t o0 = ((size_t)b * Nn + r0) * Dd + col;
        size_t o1 = ((size_t)b * Nn + r0 + 8) * Dd + col;
        float y0 = O[nb][0] * inv0, y1 = O[nb][1] * inv0;
        float y2 = O[nb][2] * inv1, y3 = O[nb][3] * inv1;
        __half2 h01 = __floats2half2_rn(y0, y1);
        __half2 h23 = __floats2half2_rn(y2, y3);
        __half2 l01 = __floats2half2_rn(y0 - __half2float(h01.x),
                                        y1 - __half2float(h01.y));
        __half2 l23 = __floats2half2_rn(y2 - __half2float(h23.x),
                                        y3 - __half2float(h23.y));
        *(__half2*)(g_y_hi + o0) = h01;
        *(__half2*)(g_y_lo + o0) = l01;
        *(__half2*)(g_y_hi + o1) = h23;
        *(__half2*)(g_y_lo + o1) = l23;
    }
}

// ---------------------------------------------------------------------------
// Kernel 5: final_mma. z = x + y @ Wf via fp16 3-term mma. K=128 single load.
// ---------------------------------------------------------------------------
static constexpr uint32_t FN_YH = 0;          // 128 x 272B = 34816
static constexpr uint32_t FN_YL = 34816;
static constexpr uint32_t FN_FH = 69632;
static constexpr uint32_t FN_FL = 104448;
static constexpr uint32_t FN_BYTES = 139264;

__global__ __launch_bounds__(256) void final_mma(
    const float* __restrict__ x,
    float* __restrict__ out)
{
    extern __shared__ char smem[];
    const uint32_t sb = smem_to_u32(smem);
    const int tid = threadIdx.x;
    const int warp = tid >> 5, lane = tid & 31;
    const int grp = lane >> 2, tg = lane & 3;
    const int m0 = blockIdx.y * 128;
    const int n0 = blockIdx.x * 128;

    #pragma unroll
    for (int it = 0; it < 8; it++) {
        int idx = tid + it * 256;
        int c = idx & 15, row = idx >> 4;
        uint32_t d = (uint32_t)row * 272u + (uint32_t)c * 16u;
        CP_ASYNC16(sb + FN_YH + d, g_y_hi + (size_t)(m0 + row) * Dd + 8 * c);
        CP_ASYNC16(sb + FN_YL + d, g_y_lo + (size_t)(m0 + row) * Dd + 8 * c);
        CP_ASYNC16(sb + FN_FH + d, g_wfT_hi + (size_t)(n0 + row) * Dd + 8 * c);
        CP_ASYNC16(sb + FN_FL + d, g_wfT_lo + (size_t)(n0 + row) * Dd + 8 * c);
    }
    CP_COMMIT();
    CP_WAIT0();
    __syncthreads();

    float O[16][4];
    #pragma unroll
    for (int i = 0; i < 16; i++)
        #pragma unroll
        for (int j = 0; j < 4; j++) O[i][j] = 0.f;

    const uint32_t a_lane = (uint32_t)(warp * 16 + (lane & 15)) * 272u
                          + (uint32_t)((lane >> 4) & 1) * 16u;
    const uint32_t b_lane = (uint32_t)((lane & 7) + ((lane & 16) ? 8 : 0)) * 272u
                          + (uint32_t)((lane & 8) ? 16 : 0);

    #pragma unroll
    for (int kc = 0; kc < 8; kc++) {
        uint32_t ah[4], al[4];
        LDSM4(ah, sb + FN_YH + a_lane + (uint32_t)kc * 32u);
        LDSM4(al, sb + FN_YL + a_lane + (uint32_t)kc * 32u);
        #pragma unroll
        for (int j = 0; j < 8; j++) {
            uint32_t bh[4], bl[4];
            uint32_t ba = sb + b_lane + (uint32_t)j * (16u * 272u) + (uint32_t)kc * 32u;
            LDSM4(bh, ba + FN_FH);
            LDSM4(bl, ba + FN_FL);
            MMAH(O[2 * j],     ah, bh[0], bh[1]);
            MMAH(O[2 * j + 1], ah, bh[2], bh[3]);
            MMAH(O[2 * j],     ah, bl[0], bl[1]);
            MMAH(O[2 * j + 1], ah, bl[2], bl[3]);
            MMAH(O[2 * j],     al, bh[0], bh[1]);
            MMAH(O[2 * j + 1], al, bh[2], bh[3]);
        }
    }

    const int r0 = m0 + warp * 16 + grp;
    #pragma unroll
    for (int nb = 0; nb < 16; nb++) {
        int col = n0 + nb * 8 + tg * 2;
        size_t o0 = (size_t)r0 * Cc + col;
        size_t o1 = (size_t)(r0 + 8) * Cc + col;
        float2 x0 = *(const float2*)(x + o0);
        float2 x1 = *(const float2*)(x + o1);
        *(float2*)(out + o0) = make_float2(O[nb][0] + x0.x, O[nb][1] + x0.y);
        *(float2*)(out + o1) = make_float2(O[nb][2] + x1.x, O[nb][3] + x1.y);
    }
}

// ---------------------------------------------------------------------------
extern "C" void kernel_launch(void* const* d_in, const int* in_sizes, int n_in,
                              void* d_out, int out_size)
{
    const float* x  = (const float*)d_in[0];
    const float* Wt = (const float*)d_in[1];
    const float* Wp = (const float*)d_in[2];
    const float* Wg = (const float*)d_in[3];
    const float* Wf = (const float*)d_in[4];
    float* out = (float*)d_out;

    cudaFuncSetAttribute(attn_kernel, cudaFuncAttributeMaxDynamicSharedMemorySize, SM_ATT_BYTES);
    cudaFuncSetAttribute(proj_mma,    cudaFuncAttributeMaxDynamicSharedMemorySize, PJ_BYTES);
    cudaFuncSetAttribute(final_mma,   cudaFuncAttributeMaxDynamicSharedMemorySize, FN_BYTES);

    // 0) presplit x and weights
    {
        int total = Bb * Nn * Cc / 4 + 3 * Cc * Dd + Dd * Cc;
        presplit_kernel<<<(total + 255) / 256, 256>>>(x, Wt, Wp, Wg, Wf);
    }

    // 1) projections via tensor cores
    proj_mma<<<dim3(128, 3), 256, PJ_BYTES>>>();

    // 2+3) fused pooling: phi split (z=2, 32x128 rows) + g transpose (z=0,1)
    pool_kernel<<<dim3(32, 4, 3), 256>>>();

    // 4) warp-MMA flash attention (R10 layout)
    attn_kernel<<<dim3(32, 4), 256, SM_ATT_BYTES>>>();

    // 5) final projection + residual via tensor cores
    final_mma<<<dim3(2, 128), 256, FN_BYTES>>>(x, out);
}